// round 17
// baseline (speedup 1.0000x reference)
#include <cuda_runtime.h>
#include <cuda_fp16.h>
#include <stdint.h>

#define MAXN 100000
#define MAXE 1600000
#define C    128

// ---------------- static device scratch ----------------
__device__ float  g_deg[MAXN];
__device__ float  g_dinv[MAXN];
__device__ int    g_count[MAXN];
__device__ int    g_off[MAXN];
__device__ int    g_cursor[MAXN];
__device__ int2   g_edat[MAXE];              // (src, norm-bits) grouped by dst
__device__ __half g_xw_h[(size_t)MAXN * C];  // GEMM output, fp16
__device__ __half g_xh[(size_t)MAXN * C];    // fp16 copy of x
__device__ __half g_hA[(size_t)MAXN * C];    // fp16 activations
__device__ __half g_hB[(size_t)MAXN * C];
__device__ __half g_Wh[3 * C * C];           // fp16 W1|W2|W3
__device__ int    g_idx32 = 0;               // monotonic: 0 = int64 idx, 1 = int32
__device__ int    g_total;                   // CSC allocation ticket

// ---------------- helpers ----------------
__device__ __forceinline__ uint32_t smem_u32(const void* p) {
    uint32_t a;
    asm("{ .reg .u64 t; cvta.to.shared.u64 t, %1; cvt.u32.u64 %0, t; }" : "=r"(a) : "l"(p));
    return a;
}
__device__ __forceinline__ void cp16(uint32_t dst, const void* src, int zf) {
    asm volatile("cp.async.cg.shared.global [%0], [%1], 16, %2;" :: "r"(dst), "l"(src), "r"(zf));
}
#define CP_COMMIT() asm volatile("cp.async.commit_group;" ::: "memory")
#define CP_WAIT(N)  asm volatile("cp.async.wait_group %0;" :: "n"(N) : "memory")

__device__ __forceinline__ void ldsm4(uint32_t* r, uint32_t addr) {
    asm volatile("ldmatrix.sync.aligned.m8n8.x4.shared.b16 {%0,%1,%2,%3}, [%4];"
                 : "=r"(r[0]), "=r"(r[1]), "=r"(r[2]), "=r"(r[3]) : "r"(addr));
}
__device__ __forceinline__ void ldsm4t(uint32_t* r, uint32_t addr) {
    asm volatile("ldmatrix.sync.aligned.m8n8.x4.trans.shared.b16 {%0,%1,%2,%3}, [%4];"
                 : "=r"(r[0]), "=r"(r[1]), "=r"(r[2]), "=r"(r[3]) : "r"(addr));
}
__device__ __forceinline__ void mma_f16(float* d, const uint32_t* a, uint32_t b0, uint32_t b1) {
    asm volatile(
        "mma.sync.aligned.m16n8k16.row.col.f32.f16.f16.f32 "
        "{%0,%1,%2,%3}, {%4,%5,%6,%7}, {%8,%9}, {%0,%1,%2,%3};"
        : "+f"(d[0]), "+f"(d[1]), "+f"(d[2]), "+f"(d[3])
        : "r"(a[0]), "r"(a[1]), "r"(a[2]), "r"(a[3]), "r"(b0), "r"(b1));
}

// ---------------- fused init + detect + fp16 pre-convert ----------------
__global__ void k_initdetect(const unsigned int* __restrict__ w, int nwords, int n,
                             const float4* __restrict__ x4,
                             const float* __restrict__ W1, const float* __restrict__ W2,
                             const float* __restrict__ W3) {
    int i = blockIdx.x * blockDim.x + threadIdx.x;
    if (i < n) { g_deg[i] = 1.0f; g_count[i] = 0; }
    if (i == 0) g_total = 0;
    unsigned int v = (i < nwords && (i & 1)) ? w[i] : 0u;
#pragma unroll
    for (int o = 16; o; o >>= 1) v |= __shfl_down_sync(0xffffffffu, v, o);
    if ((threadIdx.x & 31) == 0 && v) atomicOr(&g_idx32, 1);
    if (i < n * (C / 4)) {                       // x -> fp16 (4 floats / thread)
        float4 t = x4[i];
        __half2 h0 = __floats2half2_rn(t.x, t.y);
        __half2 h1 = __floats2half2_rn(t.z, t.w);
        *(uint2*)(g_xh + (size_t)i * 4) = make_uint2(*(uint32_t*)&h0, *(uint32_t*)&h1);
    }
    if (i < C * C) {
        g_Wh[i]             = __float2half_rn(W1[i]);
        g_Wh[C * C + i]     = __float2half_rn(W2[i]);
        g_Wh[2 * C * C + i] = __float2half_rn(W3[i]);
    }
}
__device__ __forceinline__ void load_edge(const void* ei, int i, int e, int& r, int& c) {
    if (g_idx32) {
        const int* p = (const int*)ei;
        r = p[i]; c = p[e + i];
    } else {
        const long long* p = (const long long*)ei;
        r = (int)p[i]; c = (int)p[e + i];
    }
}

// ---------------- precompute ----------------
__global__ void k_prep(const void* __restrict__ ei, const float* __restrict__ ea, int e, int n) {
    int i = blockIdx.x * blockDim.x + threadIdx.x;
    if (i >= e) return;
    int r, c;
    load_edge(ei, i, e, r, c);
    if ((unsigned)r >= (unsigned)n || (unsigned)c >= (unsigned)n) return;
    atomicAdd(&g_deg[c], ea[i]);
    atomicAdd(&g_count[c], 1);
}

// dinv + CSC segment allocation — warp-scan ticket: ONE atomic per warp
// (100k same-address atomics would serialize ~85k cycles at the LTS)
__global__ void k_alloc(int n) {
    int i = blockIdx.x * blockDim.x + threadIdx.x;
    int lane = threadIdx.x & 31;
    int cnt = (i < n) ? g_count[i] : 0;
    int s = cnt;
#pragma unroll
    for (int o = 1; o < 32; o <<= 1) {
        int t = __shfl_up_sync(0xffffffffu, s, o);
        if (lane >= o) s += t;
    }
    int wtot = __shfl_sync(0xffffffffu, s, 31);
    int base = 0;
    if (lane == 31 && wtot > 0) base = atomicAdd(&g_total, wtot);
    base = __shfl_sync(0xffffffffu, base, 31);
    if (i < n) {
        int pos = base + s - cnt;     // exclusive within warp
        g_dinv[i]   = rsqrtf(g_deg[i]);
        g_off[i]    = pos;
        g_cursor[i] = pos;
    }
}

__global__ void k_scatter(const void* __restrict__ ei, const float* __restrict__ ea, int e, int n) {
    int i = blockIdx.x * blockDim.x + threadIdx.x;
    if (i >= e) return;
    int r, c;
    load_edge(ei, i, e, r, c);
    if ((unsigned)r >= (unsigned)n || (unsigned)c >= (unsigned)n) return;
    float nm = g_dinv[r] * ea[i] * g_dinv[c];
    int pos = atomicAdd(&g_cursor[c], 1);
    g_edat[pos] = make_int2(r, __float_as_int(nm));
}
// post-scatter: segment c = [g_off[c], g_cursor[c])

// ================= persistent fp16 mma GEMM (ldmatrix), W resident =================
// 128x128 tile, 8 warps (32x64 warp tiles). fp16 smem rows pitched 272B
// (conflict-free ldmatrix + epilogue STS). W 34KB resident; X 2x34KB stages.
#define PITCHB   272                          // bytes per 128-half row
#define XSTG_B   (128 * PITCHB)               // 34816
#define SMEM_DYN (3 * XSTG_B)                 // 104448

__global__ void __launch_bounds__(256, 2) k_gemm_mma(int layer, int n, int G) {
    const __half* __restrict__ A = (layer == 0) ? g_xh : (layer == 1 ? g_hA : g_hB);
    const __half* __restrict__ Wp = g_Wh + (size_t)layer * C * C;

    extern __shared__ char sdy[];
    const uint32_t sbase = smem_u32(sdy);
    const uint32_t wbase = sbase + 2 * XSTG_B;

    const int tid  = threadIdx.x;
    const int wid  = tid >> 5;
    const int lane = tid & 31;
    const int g    = lane >> 2;
    const int tg   = lane & 3;
    const int bid  = blockIdx.x;
    const int mrow = (wid & 3) * 32;
    const int ncol = (wid >> 2) * 64;

    const int tiles = (n + 127) / 128;
    if (bid >= tiles) return;
    const int nt = (tiles - bid + G - 1) / G;

    const uint32_t lrow = (uint32_t)((lane & 7) + ((lane >> 3) & 1) * 8);
    const uint32_t lhi  = (uint32_t)((lane >> 4) & 1);
    const uint32_t aoff = lrow * PITCHB + lhi * 16;
    const uint32_t boff = lrow * PITCHB + lhi * 16 + (uint32_t)ncol * 2;

    const int srow = tid >> 1;
    const int sc0  = (tid & 1) * 8;

    // ---- W -> smem once ----
#pragma unroll
    for (int q = 0; q < 8; q++)
        cp16(wbase + srow * PITCHB + (sc0 + q) * 16,
             Wp + (size_t)srow * C + (sc0 + q) * 8, 16);

    auto stage_x = [&](int stage, int t) {
        int T   = bid + t * G;
        int row = T * 128 + srow;
        bool ok = row < n;
        const __half* s = A + (size_t)(ok ? row : 0) * C;
        int zf = ok ? 16 : 0;
        uint32_t xb = sbase + stage * XSTG_B + srow * PITCHB;
#pragma unroll
        for (int q = 0; q < 8; q++)
            cp16(xb + (sc0 + q) * 16, s + (sc0 + q) * 8, zf);
    };

    stage_x(0, 0); CP_COMMIT();    // group 0 = W + X tile0
    if (nt > 1) { stage_x(1, 1); }
    CP_COMMIT();                   // group 1 = X tile1 (possibly empty)

    for (int t = 0; t < nt; t++) {
        if (t < nt - 1) { CP_WAIT(1); } else { CP_WAIT(0); }
        __syncthreads();

        const uint32_t xs = sbase + (uint32_t)(t & 1) * XSTG_B;
        char* xsp_c = sdy + (size_t)(t & 1) * XSTG_B;

        float acc[2][8][4];
#pragma unroll
        for (int i = 0; i < 2; i++)
#pragma unroll
            for (int j = 0; j < 8; j++)
#pragma unroll
                for (int q = 0; q < 4; q++) acc[i][j][q] = 0.0f;

#pragma unroll
        for (int ks = 0; ks < 8; ks++) {
            uint32_t af[2][4], bf[4][4];
            ldsm4(af[0], xs + (uint32_t)(mrow)      * PITCHB + aoff + ks * 32);
            ldsm4(af[1], xs + (uint32_t)(mrow + 16) * PITCHB + aoff + ks * 32);
#pragma unroll
            for (int jj = 0; jj < 4; jj++)
                ldsm4t(bf[jj], wbase + (uint32_t)(ks * 16) * PITCHB + boff + jj * 32);
#pragma unroll
            for (int j = 0; j < 8; j++) {
                uint32_t b0 = bf[j >> 1][(j & 1) * 2];
                uint32_t b1 = bf[j >> 1][(j & 1) * 2 + 1];
                mma_f16(acc[0][j], af[0], b0, b1);
                mma_f16(acc[1][j], af[1], b0, b1);
            }
        }
        __syncthreads();                       // all X reads done

        // ---- epilogue: acc -> smem (conflict-free STS) -> coalesced STG ----
#pragma unroll
        for (int i = 0; i < 2; i++) {
            int rl0 = mrow + i * 16 + g;
#pragma unroll
            for (int j = 0; j < 8; j++) {
                int cc = ncol + j * 8 + 2 * tg;
                __half2 h0 = __floats2half2_rn(acc[i][j][0], acc[i][j][1]);
                __half2 h1 = __floats2half2_rn(acc[i][j][2], acc[i][j][3]);
                *(__half2*)(xsp_c + (size_t)rl0 * PITCHB + cc * 2)       = h0;
                *(__half2*)(xsp_c + (size_t)(rl0 + 8) * PITCHB + cc * 2) = h1;
            }
        }
        __syncthreads();
        {
            int grow = (bid + t * G) * 128 + srow;
            if (grow < n) {
                const char* sp = xsp_c + (size_t)srow * PITCHB;
#pragma unroll
                for (int q = 0; q < 8; q++) {
                    uint4 v = *(const uint4*)(sp + (sc0 + q) * 16);
                    *(uint4*)(g_xw_h + (size_t)grow * C + (sc0 + q) * 8) = v;
                }
            }
        }
        __syncthreads();                       // epilogue reads done before restage
        if (t + 2 < nt) { stage_x(t & 1, t + 2); }
        CP_COMMIT();                           // keep group count in lockstep
    }
}

// ---------------- aggregation (fp16 gathers), fp16 activation output ----------------
__global__ void __launch_bounds__(256) k_agg(const float* __restrict__ bias, int dst, int n) {
    __half* __restrict__ out = dst ? g_hB : g_hA;
    int warp = (blockIdx.x * blockDim.x + threadIdx.x) >> 5;
    int lane = threadIdx.x & 31;
    if (warp >= n) return;
    float dv = g_dinv[warp];
    float sw = dv * dv;
    uint2 su = *(const uint2*)(g_xw_h + (size_t)warp * C + lane * 4);
    float2 s0 = __half22float2(*(__half2*)&su.x);
    float2 s1 = __half22float2(*(__half2*)&su.y);
    float a0 = sw * s0.x, a1 = sw * s0.y, a2 = sw * s1.x, a3 = sw * s1.y;
    int s = g_off[warp], e = g_cursor[warp];
    for (int j = s; j < e; j++) {
        int2 ed = g_edat[j];
        float nm = __int_as_float(ed.y);
        uint2 u = *(const uint2*)(g_xw_h + (size_t)ed.x * C + lane * 4);
        float2 p0 = __half22float2(*(__half2*)&u.x);
        float2 p1 = __half22float2(*(__half2*)&u.y);
        a0 = fmaf(nm, p0.x, a0);
        a1 = fmaf(nm, p0.y, a1);
        a2 = fmaf(nm, p1.x, a2);
        a3 = fmaf(nm, p1.y, a3);
    }
    float4 bb = ((const float4*)bias)[lane];
    __half2 h0 = __floats2half2_rn(fmaxf(a0 + bb.x, 0.f), fmaxf(a1 + bb.y, 0.f));
    __half2 h1 = __floats2half2_rn(fmaxf(a2 + bb.z, 0.f), fmaxf(a3 + bb.w, 0.f));
    *(uint2*)(out + (size_t)warp * C + lane * 4) = make_uint2(*(uint32_t*)&h0, *(uint32_t*)&h1);
}

// ---------------- fused layer-3 aggregation + linear head ----------------
__global__ void __launch_bounds__(256) k_agg_head(const float* __restrict__ bias,
                                                  const float* __restrict__ lw,
                                                  const float* __restrict__ lb,
                                                  float* __restrict__ outp, int n) {
    int warp = (blockIdx.x * blockDim.x + threadIdx.x) >> 5;
    int lane = threadIdx.x & 31;
    if (warp >= n) return;
    float dv = g_dinv[warp];
    float sw = dv * dv;
    uint2 su = *(const uint2*)(g_xw_h + (size_t)warp * C + lane * 4);
    float2 s0 = __half22float2(*(__half2*)&su.x);
    float2 s1 = __half22float2(*(__half2*)&su.y);
    float a0 = sw * s0.x, a1 = sw * s0.y, a2 = sw * s1.x, a3 = sw * s1.y;
    int s = g_off[warp], e = g_cursor[warp];
    for (int j = s; j < e; j++) {
        int2 ed = g_edat[j];
        float nm = __int_as_float(ed.y);
        uint2 u = *(const uint2*)(g_xw_h + (size_t)ed.x * C + lane * 4);
        float2 p0 = __half22float2(*(__half2*)&u.x);
        float2 p1 = __half22float2(*(__half2*)&u.y);
        a0 = fmaf(nm, p0.x, a0);
        a1 = fmaf(nm, p0.y, a1);
        a2 = fmaf(nm, p1.x, a2);
        a3 = fmaf(nm, p1.y, a3);
    }
    float4 bb = ((const float4*)bias)[lane];
    float4 w  = ((const float4*)lw)[lane];
    float sdot = fmaxf(a0 + bb.x, 0.f) * w.x
               + fmaxf(a1 + bb.y, 0.f) * w.y
               + fmaxf(a2 + bb.z, 0.f) * w.z
               + fmaxf(a3 + bb.w, 0.f) * w.w;
#pragma unroll
    for (int o = 16; o; o >>= 1) sdot += __shfl_down_sync(0xffffffffu, sdot, o);
    if (lane == 0) outp[warp] = sdot + lb[0];
}

// ---------------- host launch ----------------
extern "C" void kernel_launch(void* const* d_in, const int* in_sizes, int n_in,
                              void* d_out, int out_size) {
    const float* x  = (const float*)d_in[0];
    const void*  ei = d_in[1];
    const float* ea = (const float*)d_in[2];
    const float* W1 = (const float*)d_in[3];
    const float* b1 = (const float*)d_in[4];
    const float* W2 = (const float*)d_in[5];
    const float* b2 = (const float*)d_in[6];
    const float* W3 = (const float*)d_in[7];
    const float* b3 = (const float*)d_in[8];
    const float* lw = (const float*)d_in[9];
    const float* lb = (const float*)d_in[10];
    float* outp = (float*)d_out;

    int n = in_sizes[0] / C;
    int e = in_sizes[2];
    if (n > MAXN) n = MAXN;
    if (e > MAXE) e = MAXE;

    const int nbE   = (e + 255) / 256;
    const int nbN   = (n + 255) / 256;
    const int nbDet = (2 * e + 255) / 256;
    const int nbW   = (n * 32 + 255) / 256;
    const int tiles = (n + 127) / 128;
    int G = 2 * 148;
    if (G > tiles) G = tiles;

    cudaFuncSetAttribute(k_gemm_mma, cudaFuncAttributeMaxDynamicSharedMemorySize, SMEM_DYN);

    k_initdetect<<<nbDet, 256>>>((const unsigned int*)ei, 2 * e, n,
                                 (const float4*)x, W1, W2, W3);             // 1
    k_prep      <<<nbE, 256>>>(ei, ea, e, n);                               // 2
    k_alloc     <<<nbN, 256>>>(n);                                          // 3
    k_gemm_mma  <<<G, 256, SMEM_DYN>>>(0, n, G);                            // 4 <- profiled
    k_scatter   <<<nbE, 256>>>(ei, ea, e, n);                               // 5
    k_agg       <<<nbW, 256>>>(b1, 0, n);                                   // 6  -> hA
    k_gemm_mma  <<<G, 256, SMEM_DYN>>>(1, n, G);                            // 7
    k_agg       <<<nbW, 256>>>(b2, 1, n);                                   // 8  -> hB
    k_gemm_mma  <<<G, 256, SMEM_DYN>>>(2, n, G);                            // 9
    k_agg_head  <<<nbW, 256>>>(b3, lw, lb, outp, n);                        // 10
}